// round 1
// baseline (speedup 1.0000x reference)
#include <cuda_runtime.h>
#include <cstdint>

#define BB 64
#define MM 2048
#define DD 512
#define BLOCKS_PER_B 32
#define ROWS_PER_BLOCK (MM / BLOCKS_PER_B)   // 64
#define WARPS_PER_BLOCK 8
#define ROWS_PER_WARP (ROWS_PER_BLOCK / WARPS_PER_BLOCK)  // 8

// Per-batch best: high 32 bits = float bits of squared distance (non-negative,
// so bit pattern is monotone), low 32 bits = (MM-1-idx) so that on ties the
// SMALLEST index wins under atomicMax (matches jnp.argmax first-occurrence).
__device__ unsigned long long g_best[BB];

__global__ void knn_init_kernel() {
    if (threadIdx.x < BB) g_best[threadIdx.x] = 0ULL;
}

__global__ __launch_bounds__(256) void knn_dist_kernel(
    const float* __restrict__ inputs,   // [BB, DD]
    const float* __restrict__ buffer)   // [BB, MM, DD]
{
    __shared__ float s_in[DD];

    const int b     = blockIdx.x / BLOCKS_PER_B;
    const int chunk = blockIdx.x % BLOCKS_PER_B;

    // Stage the query row into smem (2 KB), fully coalesced.
    for (int i = threadIdx.x; i < DD / 4; i += blockDim.x) {
        reinterpret_cast<float4*>(s_in)[i] =
            reinterpret_cast<const float4*>(inputs + (size_t)b * DD)[i];
    }
    __syncthreads();

    const int warp = threadIdx.x >> 5;
    const int lane = threadIdx.x & 31;

    // Each lane keeps its 16 query floats in registers (4x float4 strided by 32).
    float4 q[4];
#pragma unroll
    for (int i = 0; i < 4; i++)
        q[i] = reinterpret_cast<const float4*>(s_in)[lane + i * 32];

    float best_dist = -1.0f;
    int   best_m    = 0;

    const int m0 = chunk * ROWS_PER_BLOCK + warp * ROWS_PER_WARP;
    const float* base = buffer + ((size_t)b * MM + (size_t)m0) * DD;

#pragma unroll
    for (int r = 0; r < ROWS_PER_WARP; r++) {
        const float4* row = reinterpret_cast<const float4*>(base + (size_t)r * DD);
        float acc = 0.0f;
#pragma unroll
        for (int i = 0; i < 4; i++) {
            float4 v = row[lane + i * 32];
            float dx = v.x - q[i].x;
            float dy = v.y - q[i].y;
            float dz = v.z - q[i].z;
            float dw = v.w - q[i].w;
            acc = fmaf(dx, dx, acc);
            acc = fmaf(dy, dy, acc);
            acc = fmaf(dz, dz, acc);
            acc = fmaf(dw, dw, acc);
        }
        // Warp tree-reduce (result replicated to all lanes).
#pragma unroll
        for (int o = 16; o > 0; o >>= 1)
            acc += __shfl_xor_sync(0xFFFFFFFFu, acc, o);

        if (acc > best_dist) { best_dist = acc; best_m = m0 + r; }
    }

    if (lane == 0) {
        unsigned long long packed =
            ((unsigned long long)__float_as_uint(best_dist) << 32) |
            (unsigned int)(MM - 1 - best_m);
        atomicMax(&g_best[b], packed);
    }
}

__global__ void knn_gather_kernel(const float* __restrict__ buffer,
                                  float* __restrict__ out)
{
    const int b = blockIdx.x;
    const unsigned long long p = g_best[b];
    const int idx = MM - 1 - (int)(unsigned int)(p & 0xFFFFFFFFu);

    const float4* src =
        reinterpret_cast<const float4*>(buffer + ((size_t)b * MM + (size_t)idx) * DD);
    float4* dst = reinterpret_cast<float4*>(out + (size_t)b * DD);

    for (int i = threadIdx.x; i < DD / 4; i += blockDim.x)
        dst[i] = src[i];
}

extern "C" void kernel_launch(void* const* d_in, const int* in_sizes, int n_in,
                              void* d_out, int out_size)
{
    const float* inputs;
    const float* buffer;
    // inputs has BB*DD = 32768 elems, buffer has BB*MM*DD = 67108864.
    if (in_sizes[0] == BB * DD) {
        inputs = (const float*)d_in[0];
        buffer = (const float*)d_in[1];
    } else {
        inputs = (const float*)d_in[1];
        buffer = (const float*)d_in[0];
    }
    float* out = (float*)d_out;

    knn_init_kernel<<<1, 64>>>();
    knn_dist_kernel<<<BB * BLOCKS_PER_B, 256>>>(inputs, buffer);
    knn_gather_kernel<<<BB, 128>>>(buffer, out);
}

// round 2
// speedup vs baseline: 1.0776x; 1.0776x over previous
#include <cuda_runtime.h>
#include <cstdint>

#define BB 64
#define MM 2048
#define DD 512
#define BLOCKS_PER_B 32
#define ROWS_PER_BLOCK (MM / BLOCKS_PER_B)   // 64
#define WARPS_PER_BLOCK 8
#define ROWS_PER_WARP (ROWS_PER_BLOCK / WARPS_PER_BLOCK)  // 8

// Per-(batch, chunk) partial: high 32 bits = float bits of squared distance
// (non-negative -> bit pattern monotone), low 32 bits = (MM-1-idx) so that on
// ties the SMALLEST index wins under max (matches jnp.argmax first-occurrence).
__device__ unsigned long long g_part[BB * BLOCKS_PER_B];
// Per-batch arrival counter. Zero-initialized at module load; the finishing
// block resets it to 0 so every graph replay starts from a clean state.
__device__ int g_cnt[BB];

__global__ __launch_bounds__(256) void knn_fused_kernel(
    const float* __restrict__ inputs,   // [BB, DD]
    const float* __restrict__ buffer,   // [BB, MM, DD]
    float* __restrict__ out)            // [BB, DD]
{
    __shared__ float s_in[DD];
    __shared__ unsigned long long s_warp_best[WARPS_PER_BLOCK];
    __shared__ int s_idx;

    const int b     = blockIdx.x / BLOCKS_PER_B;
    const int chunk = blockIdx.x % BLOCKS_PER_B;

    // Stage the query row into smem (2 KB), fully coalesced.
    for (int i = threadIdx.x; i < DD / 4; i += blockDim.x) {
        reinterpret_cast<float4*>(s_in)[i] =
            reinterpret_cast<const float4*>(inputs + (size_t)b * DD)[i];
    }
    __syncthreads();

    const int warp = threadIdx.x >> 5;
    const int lane = threadIdx.x & 31;

    // Each lane keeps its 16 query floats in registers (4x float4 strided by 32).
    float4 q[4];
#pragma unroll
    for (int i = 0; i < 4; i++)
        q[i] = reinterpret_cast<const float4*>(s_in)[lane + i * 32];

    float best_dist = -1.0f;
    int   best_m    = 0;

    const int m0 = chunk * ROWS_PER_BLOCK + warp * ROWS_PER_WARP;
    const float* base = buffer + ((size_t)b * MM + (size_t)m0) * DD;

#pragma unroll
    for (int r = 0; r < ROWS_PER_WARP; r++) {
        const float4* row = reinterpret_cast<const float4*>(base + (size_t)r * DD);
        float acc = 0.0f;
#pragma unroll
        for (int i = 0; i < 4; i++) {
            float4 v = __ldg(row + lane + i * 32);
            float dx = v.x - q[i].x;
            float dy = v.y - q[i].y;
            float dz = v.z - q[i].z;
            float dw = v.w - q[i].w;
            acc = fmaf(dx, dx, acc);
            acc = fmaf(dy, dy, acc);
            acc = fmaf(dz, dz, acc);
            acc = fmaf(dw, dw, acc);
        }
        // Warp tree-reduce (result replicated to all lanes).
#pragma unroll
        for (int o = 16; o > 0; o >>= 1)
            acc += __shfl_xor_sync(0xFFFFFFFFu, acc, o);

        if (acc > best_dist) { best_dist = acc; best_m = m0 + r; }
    }

    // Per-warp packed best -> smem, block reduce in warp 0.
    if (lane == 0) {
        s_warp_best[warp] =
            ((unsigned long long)__float_as_uint(best_dist) << 32) |
            (unsigned int)(MM - 1 - best_m);
    }
    __syncthreads();

    if (threadIdx.x == 0) {
        unsigned long long blk = 0ULL;
#pragma unroll
        for (int w = 0; w < WARPS_PER_BLOCK; w++)
            blk = max(blk, s_warp_best[w]);
        g_part[b * BLOCKS_PER_B + chunk] = blk;
        __threadfence();
        int arrived = atomicAdd(&g_cnt[b], 1);
        s_idx = (arrived == BLOCKS_PER_B - 1) ? 1 : 0;
    }
    __syncthreads();

    // Last-arriving block of this batch: reduce all 32 partials + gather.
    if (s_idx) {
        if (warp == 0) {
            unsigned long long v = g_part[b * BLOCKS_PER_B + lane];
#pragma unroll
            for (int o = 16; o > 0; o >>= 1) {
                unsigned long long u = __shfl_xor_sync(0xFFFFFFFFu, v, o);
                v = max(v, u);
            }
            if (lane == 0) {
                s_idx = MM - 1 - (int)(unsigned int)(v & 0xFFFFFFFFu);
                g_cnt[b] = 0;   // reset for next graph replay
            }
        }
        __syncthreads();

        const int idx = s_idx;
        const float4* src = reinterpret_cast<const float4*>(
            buffer + ((size_t)b * MM + (size_t)idx) * DD);
        float4* dst = reinterpret_cast<float4*>(out + (size_t)b * DD);
        // 128 float4 elements; first 128 threads each copy one.
        if (threadIdx.x < DD / 4)
            dst[threadIdx.x] = src[threadIdx.x];
    }
}

extern "C" void kernel_launch(void* const* d_in, const int* in_sizes, int n_in,
                              void* d_out, int out_size)
{
    const float* inputs;
    const float* buffer;
    // inputs has BB*DD = 32768 elems, buffer has BB*MM*DD = 67108864.
    if (in_sizes[0] == BB * DD) {
        inputs = (const float*)d_in[0];
        buffer = (const float*)d_in[1];
    } else {
        inputs = (const float*)d_in[1];
        buffer = (const float*)d_in[0];
    }
    float* out = (float*)d_out;

    knn_fused_kernel<<<BB * BLOCKS_PER_B, 256>>>(inputs, buffer, out);
}